// round 10
// baseline (speedup 1.0000x reference)
#include <cuda_runtime.h>

// Problem constants (fixed by setup_inputs): B=8, N=16384, K=64
#define BB    8
#define NN    16384
#define KK    64
#define MTOT  (BB * NN)            // 131072 points total
#define NROWS (BB * KK)            // 512 (b,k) rows
#define NHALF (NROWS * 2)          // 1024 half-row BN units
// inv = -1/(2*sigma^2) = -12.5 ;  C = inv * log2(e)
#define CLOG2 (-18.033688011112043f)

#define GRID  444                  // 3 CTAs/SM on 148 SMs, all co-resident
#define TPB   256
#define PTS_PER_UNIT 32
#define NUNIT (MTOT / PTS_PER_UNIT)   // 4096 work units for stages A and B

// Scratch (no cudaMalloc allowed)
__device__ float  g_h[(size_t)MTOT * KK];   // 33.5 MB: h[b][j][k], k contiguous
__device__ double g_sum[KK];
__device__ double g_ssum[KK];
__device__ unsigned g_workA;
__device__ unsigned g_workB;
__device__ unsigned g_arrive;               // grid barrier, monotonic across replays
__device__ volatile unsigned g_release;

__device__ __forceinline__ float ex2f(float x) {
    float r;
    asm("ex2.approx.ftz.f32 %0, %1;" : "=f"(r) : "f"(x));
    return r;
}

// Software grid barrier. Monotonic epoch counters -> safe across graph replays.
__device__ __forceinline__ void gsync() {
    __syncthreads();
    if (threadIdx.x == 0) {
        __threadfence();
        unsigned t = atomicAdd(&g_arrive, 1u);
        unsigned ep = t / GRID + 1u;
        if (t % GRID == GRID - 1u) {
            g_release = ep;
        } else {
            while (g_release < ep) { __nanosleep(64); }
        }
        __threadfence();
    }
    __syncthreads();
}

__global__ void __launch_bounds__(TPB, 3) fkc_fused(
    const float* __restrict__ normals,
    const void*  __restrict__ nidx,
    const float* __restrict__ wa,
    const float* __restrict__ wb,
    const float* __restrict__ gamma,
    const float* __restrict__ beta,
    float* __restrict__ out)
{
    __shared__ float sT[PTS_PER_UNIT * 65];   // padded transpose tile (8320 B)
    __shared__ float sredS[TPB], sredSS[TPB];
    __shared__ int   sJ[PTS_PER_UNIT * 3];    // staged neighbor indices per unit
    __shared__ int   sIdx32;
    __shared__ unsigned sChunk;

    const int tid = threadIdx.x;
    const int k   = tid & 63;        // this thread's channel (fixed for whole kernel)
    const int pg  = tid >> 6;        // point subgroup 0..3

    // Per-thread weights for its k: w' = -2C * w ; we = exp2(C*||w||^2)/16
    float Wx[4], Wy[4], Wz[4], We[4];
#pragma unroll
    for (int m = 0; m < 4; m++) {
        float a = __ldg(wa + k * 4 + m), b = __ldg(wb + k * 4 + m);
        float sa, ca, sb, cb;
        sincosf(a, &sa, &ca);
        sincosf(b, &sb, &cb);
        float wx = sa * cb, wy = sa * sb, wz = ca;
        float W2 = wx * wx + wy * wy + wz * wz;
        const float s = -2.0f * CLOG2;
        Wx[m] = wx * s; Wy[m] = wy * s; Wz[m] = wz * s;
        We[m] = exp2f(CLOG2 * W2) * (1.0f / 16.0f);
    }
    if (tid == 0) {
        // Probe int32 (JAX default) vs int64 neighbor_idx
        int is32 = 0;
        const long long* p = (const long long*)nidx;
        for (int j = 0; j < 8; j++) {
            long long v = p[j];
            if (v < 0 || v >= NN) is32 = 1;
        }
        sIdx32 = is32;
    }
    if (blockIdx.x == 0 && tid < KK) { g_sum[tid] = 0.0; g_ssum[tid] = 0.0; }
    __syncthreads();
    const int idx32 = sIdx32;

    // ------------ Stage A: h[b][j][k] for every face-point normal ----------
    for (;;) {
        if (tid == 0) sChunk = atomicAdd(&g_workA, 1u);
        __syncthreads();
        unsigned u = sChunk;
        __syncthreads();
        if (u >= NUNIT) break;

        int base = (int)u * PTS_PER_UNIT;
#pragma unroll
        for (int sub = 0; sub < 8; sub++) {
            int pid = base + sub * 4 + pg;
            int b = pid >> 14;
            int n = pid & (NN - 1);
            const float* nb = normals + (size_t)b * (3 * NN);
            float x = __ldg(nb + n);
            float y = __ldg(nb + NN + n);
            float z = __ldg(nb + 2 * NN + n);
            float cf2 = CLOG2 * fmaf(x, x, fmaf(y, y, z * z));
            float sum = 0.f;
#pragma unroll
            for (int m = 0; m < 4; m++) {
                float d = fmaf(x, Wx[m], fmaf(y, Wy[m], fmaf(z, Wz[m], cf2)));
                sum = fmaf(ex2f(d), We[m], sum);
            }
            g_h[(size_t)pid * KK + k] = sum;   // lanes k-consecutive -> coalesced
        }
    }

    gsync();   // all h written, stats zeroed
    if (blockIdx.x == 0 && tid == 0) g_workA = 0;   // reset for next replay

    // ------------ Stage B: gather-sum + transpose-write + fused stats ------
    float s = 0.f, ss = 0.f;
    for (;;) {
        if (tid == 0) sChunk = atomicAdd(&g_workB, 1u);
        __syncthreads();
        unsigned u = sChunk;
        if (u >= NUNIT) break;

        int base = (int)u * PTS_PER_UNIT;
        int b  = base >> 14;
        int n0 = base & (NN - 1);
        const float* hb = g_h + (size_t)b * NN * KK;

        // Stage neighbor indices for these 32 points (96 ints) into smem
        if (tid < PTS_PER_UNIT * 3) {
            size_t rowbase = ((size_t)b * NN + n0) * 3;
            if (idx32) sJ[tid] = ((const int*)nidx)[rowbase + tid];
            else       sJ[tid] = (int)((const long long*)nidx)[rowbase + tid];
        }
        __syncthreads();

#pragma unroll
        for (int sub = 0; sub < 8; sub++) {
            int pt = sub * 4 + pg;
            int n  = n0 + pt;
            int j1 = sJ[pt * 3 + 0], j2 = sJ[pt * 3 + 1], j3 = sJ[pt * 3 + 2];
            float v = hb[(size_t)n * KK + k]
                    + hb[(size_t)j1 * KK + k]
                    + hb[(size_t)j2 * KK + k]
                    + hb[(size_t)j3 * KK + k];
            sT[pt * 65 + k] = v;
            s += v;
            ss = fmaf(v, v, ss);
        }
        __syncthreads();

        // Transposed write: lanes cover n -> 128B-coalesced stores
        {
            int nl = tid & 31;
            int kb = tid >> 5;          // 0..7
            float* ob = out + (size_t)b * KK * NN + n0 + nl;
#pragma unroll
            for (int i = 0; i < 8; i++) {
                int kr = kb * 8 + i;
                ob[(size_t)kr * NN] = sT[nl * 65 + kr];
            }
        }
        __syncthreads();   // protects sT/sJ reuse and sChunk rewrite
    }

    // Block-level stats reduction: threads tid, tid+64, tid+128, tid+192 share k
    sredS[tid] = s; sredSS[tid] = ss;
    __syncthreads();
    if (tid < KK) {
        float ts  = sredS[tid]  + sredS[tid + 64]  + sredS[tid + 128]  + sredS[tid + 192];
        float tss = sredSS[tid] + sredSS[tid + 64] + sredSS[tid + 128] + sredSS[tid + 192];
        atomicAdd(&g_sum[tid],  (double)ts);
        atomicAdd(&g_ssum[tid], (double)tss);
    }

    gsync();   // all stats accumulated
    if (blockIdx.x == 0 && tid == 0) g_workB = 0;   // reset for next replay

    // ------------ Stage C: BN + ReLU in place (L2-resident) ----------------
    for (int h = blockIdx.x; h < NHALF; h += GRID) {
        int r = h >> 1;
        int kk = r & (KK - 1);
        double mean = g_sum[kk] * (1.0 / MTOT);
        double var  = g_ssum[kk] * (1.0 / MTOT) - mean * mean;
        float sc = __ldg(gamma + kk) * rsqrtf((float)var + 1e-5f);
        float sh = __ldg(beta + kk) - (float)mean * sc;
        float4* p4 = (float4*)(out + (size_t)r * NN + (h & 1) * (NN / 2));
#pragma unroll
        for (int i = 0; i < NN / 8 / TPB; i++) {   // 8 iterations
            float4 v = p4[i * TPB + tid];
            v.x = fmaxf(fmaf(v.x, sc, sh), 0.f);
            v.y = fmaxf(fmaf(v.y, sc, sh), 0.f);
            v.z = fmaxf(fmaf(v.z, sc, sh), 0.f);
            v.w = fmaxf(fmaf(v.w, sc, sh), 0.f);
            p4[i * TPB + tid] = v;
        }
    }
}

extern "C" void kernel_launch(void* const* d_in, const int* in_sizes, int n_in,
                              void* d_out, int out_size) {
    const float* normals = (const float*)d_in[0];
    const void*  nidx    = d_in[1];
    const float* wa      = (const float*)d_in[2];
    const float* wb      = (const float*)d_in[3];
    const float* gamma   = (const float*)d_in[4];
    const float* beta    = (const float*)d_in[5];
    float* out = (float*)d_out;

    fkc_fused<<<GRID, TPB>>>(normals, nidx, wa, wb, gamma, beta, out);
}